// round 11
// baseline (speedup 1.0000x reference)
#include <cuda_runtime.h>
#include <stdint.h>

#define D_FEAT   256
#define D4       (D_FEAT / 4)     // 64 float4 per x row
#define OUTW     (2 * D_FEAT)     // 512 floats per output row
#define MAX_N    32768
#define MAX_B    8192
#define CAP      128              // slots per destination row (mean deg ~16, max ~45)
#define MAX_SP   65536            // spill capacity (normally 0 used)
#define NT       256
#define MAX_CTA_PER_SM 4

// Scratch (no cudaMalloc allowed) — device globals
__device__ int   g_deg[MAX_N];
__device__ int   g_cntrow[MAX_B];
__device__ int   g_idx64;
__device__ int   g_spill;
__device__ int   g_ticket;
__device__ int   g_slots[MAX_B * CAP];
__device__ int2  g_sp_edge[MAX_SP];

// generation-based grid barrier state (monotonic across graph replays)
__device__ int           g_bar_count;
__device__ volatile int  g_bar_gen;

__device__ __forceinline__ void grid_barrier(int nblocks) {
    __syncthreads();
    if (threadIdx.x == 0) {
        int gen = g_bar_gen;
        __threadfence();                       // make prior writes visible
        if (atomicAdd(&g_bar_count, 1) == nblocks - 1) {
            g_bar_count = 0;
            __threadfence();
            g_bar_gen = gen + 1;               // release
        } else {
            while (g_bar_gen == gen) __nanosleep(32);
            __threadfence();                   // acquire
        }
    }
    __syncthreads();
}

__device__ __forceinline__ int load_idx(const void* ei, long long i, int is64) {
    return is64 ? (int)((const long long*)ei)[i] : ((const int*)ei)[i];
}

__device__ __forceinline__ void fma4(float4& a, float w, const float4& v) {
    a.x += w * v.x; a.y += w * v.y; a.z += w * v.z; a.w += w * v.w;
}

__device__ __forceinline__ void build_edge(int src, int dst, int batch) {
    atomicAdd(&g_deg[src], 1);
    if (dst < batch) {
        int slot = atomicAdd(&g_cntrow[dst], 1);
        if (slot < CAP) {
            g_slots[dst * CAP + slot] = src;
        } else {
            int p = atomicAdd(&g_spill, 1);
            if (p < MAX_SP) g_sp_edge[p] = make_int2(src, dst);
        }
    }
}

// ---------------------------------------------------------------------------
__global__ void __launch_bounds__(NT, MAX_CTA_PER_SM)
k_fused(const void* __restrict__ ei, const float4* __restrict__ x4,
        float4* __restrict__ out4, int E, int n, int batch, int nblocks) {
    const int tid      = blockIdx.x * NT + threadIdx.x;
    const int nthreads = nblocks * NT;

    // ---- Phase A: zero counters, detect index dtype -------------------------
    for (int i = tid; i < n; i += nthreads) g_deg[i] = 0;
    for (int i = tid; i < batch; i += nthreads) g_cntrow[i] = 0;
    if (tid == 0) { g_spill = 0; g_ticket = 0; }

    if (blockIdx.x == 0) {
        __shared__ int bad;
        if (threadIdx.x == 0) bad = 0;
        __syncthreads();
        const long long* e64 = (const long long*)ei;
        int K = min(E, 2048);
        for (int t = threadIdx.x; t < K; t += NT) {
            long long v = e64[t];
            if (v < 0 || v >= (long long)n) bad = 1;
        }
        __syncthreads();
        if (threadIdx.x == 0) g_idx64 = bad ? 0 : 1;
    }

    grid_barrier(nblocks);

    // ---- Phase B: build deg + slot buckets (int4-vectorized fast path) ------
    const int is64 = g_idx64;
    if (!is64 && (E & 3) == 0) {
        const int4* s4 = (const int4*)ei;
        const int4* d4 = (const int4*)((const int*)ei + E);
        int nq = E >> 2;
        for (int q = tid; q < nq; q += nthreads) {
            int4 s = s4[q];
            int4 d = d4[q];
            build_edge(s.x, d.x, batch);
            build_edge(s.y, d.y, batch);
            build_edge(s.z, d.z, batch);
            build_edge(s.w, d.w, batch);
        }
    } else {
        for (int i = tid; i < E; i += nthreads) {
            int src = load_idx(ei, i, is64);
            int dst = load_idx(ei, (long long)E + i, is64);
            build_edge(src, dst, batch);
        }
    }

    grid_barrier(nblocks);

    // ---- Phase C: gather, dynamic half-row tasks (work stealing) ------------
    // task = row * 2 + half; each warp owns 32 float4 columns of one row.
    const int lane   = threadIdx.x & 31;
    const int ntasks = batch * 2;

    for (;;) {
        int task;
        if (lane == 0) task = atomicAdd(&g_ticket, 1);
        task = __shfl_sync(0xffffffff, task, 0);
        if (task >= ntasks) break;

        int row = task >> 1;
        int col = ((task & 1) << 5) + lane;        // float4 column within x row

        int mraw = g_cntrow[row];
        int m = (mraw > CAP) ? CAP : mraw;
        int dr = g_deg[row];
        float disr = (dr > 0) ? rsqrtf((float)dr) : 0.0f;

        float4 a = make_float4(0.f, 0.f, 0.f, 0.f);

        const int* srow = g_slots + row * CAP;
        for (int base = 0; base < m; base += 32) {
            int e = base + lane;
            int cnt = min(32, m - base);
            int   psrc = 0;
            float pw   = 0.0f;
            if (e < m) {
                psrc = srow[e];
                pw = rsqrtf((float)g_deg[psrc]) * disr;   // deg[src] >= 1 always
            }
            for (int t = 0; t < cnt; t++) {
                int   s  = __shfl_sync(0xffffffff, psrc, t);
                float ww = __shfl_sync(0xffffffff, pw, t);
                float4 v = __ldg(&x4[(size_t)s * D4 + col]);
                fma4(a, ww, v);
            }
        }

        // Overflow fold (only the owning row's warps touch its spilled edges).
        if (mraw > CAP) {
            int sp = g_spill;
            if (sp > MAX_SP) sp = MAX_SP;
            for (int base = 0; base < sp; base += 32) {
                int e = base + lane;
                int cnt = min(32, sp - base);
                int   psrc = 0;
                float pw   = 0.0f;
                if (e < sp) {
                    int2 ed = g_sp_edge[e];
                    if (ed.y == row) {
                        psrc = ed.x;
                        pw = rsqrtf((float)g_deg[psrc]) * disr;
                    }
                }
                for (int t = 0; t < cnt; t++) {
                    float ww = __shfl_sync(0xffffffff, pw, t);
                    if (ww == 0.0f) continue;
                    int s = __shfl_sync(0xffffffff, psrc, t);
                    float4 v = __ldg(&x4[(size_t)s * D4 + col]);
                    fma4(a, ww, v);
                }
            }
        }

        // write this warp's 32 columns: x copy + aggregated half
        float4* o = out4 + (size_t)row * (OUTW / 4);
        o[col]      = __ldg(&x4[(size_t)row * D4 + col]);
        o[col + 64] = a;
    }
}

// ---------------------------------------------------------------------------
extern "C" void kernel_launch(void* const* d_in, const int* in_sizes, int n_in,
                              void* d_out, int out_size) {
    // Identify inputs by element count (robust to metadata ordering).
    int ix = 0, ie = -1;
    for (int i = 1; i < n_in; i++)
        if (in_sizes[i] > in_sizes[ix]) ix = i;
    for (int i = 0; i < n_in; i++) {
        if (i == ix || in_sizes[i] <= 1) continue;
        if (ie < 0 || in_sizes[i] > in_sizes[ie]) ie = i;
    }
    if (ie < 0) ie = (ix == 0) ? 1 : 0;

    const float* x  = (const float*)d_in[ix];
    const void*  ei = d_in[ie];

    int n     = in_sizes[ix] / D_FEAT;         // 20000
    int E     = in_sizes[ie] / 2;              // 320000
    int batch = out_size / OUTW;               // 4096

    // Co-resident grid: query achievable occupancy so the spin barrier is safe.
    static int nblocks = 0;
    if (nblocks == 0) {
        int smCount = 0;
        if (cudaDeviceGetAttribute(&smCount, cudaDevAttrMultiProcessorCount, 0)
            != cudaSuccess || smCount <= 0)
            smCount = 148;
        int perSM = 0;
        if (cudaOccupancyMaxActiveBlocksPerMultiprocessor(&perSM, k_fused, NT, 0)
            != cudaSuccess || perSM <= 0)
            perSM = 1;
        if (perSM > MAX_CTA_PER_SM) perSM = MAX_CTA_PER_SM;
        nblocks = smCount * perSM;
    }

    k_fused<<<nblocks, NT>>>(ei, (const float4*)x, (float4*)d_out,
                             E, n, batch, nblocks);
}

// round 12
// speedup vs baseline: 1.0817x; 1.0817x over previous
#include <cuda_runtime.h>
#include <stdint.h>

#define D_FEAT   256
#define D4       (D_FEAT / 4)     // 64 float4 per x row
#define OUTW     (2 * D_FEAT)     // 512 floats per output row
#define MAX_N    32768
#define MAX_B    8192
#define CAP      128              // slots per destination row (mean deg ~16, max ~45)
#define MAX_SP   65536            // spill capacity (normally 0 used)
#define NT       256
#define NWARP    (NT / 32)
#define PIPE     6                // cp.async pipeline depth (1KB x-row per stage)
#define MAX_CTA_PER_SM 4

// Scratch (no cudaMalloc allowed) — device globals
__device__ int   g_deg[MAX_N];
__device__ int   g_cntrow[MAX_B];
__device__ int   g_idx64;
__device__ int   g_spill;
__device__ int   g_slots[MAX_B * CAP];
__device__ int2  g_sp_edge[MAX_SP];

// generation-based grid barrier state (monotonic across graph replays)
__device__ int           g_bar_count;
__device__ volatile int  g_bar_gen;

__device__ __forceinline__ void grid_barrier(int nblocks) {
    __syncthreads();
    if (threadIdx.x == 0) {
        int gen = g_bar_gen;
        __threadfence();
        if (atomicAdd(&g_bar_count, 1) == nblocks - 1) {
            g_bar_count = 0;
            __threadfence();
            g_bar_gen = gen + 1;
        } else {
            while (g_bar_gen == gen) __nanosleep(32);
            __threadfence();
        }
    }
    __syncthreads();
}

__device__ __forceinline__ int load_idx(const void* ei, long long i, int is64) {
    return is64 ? (int)((const long long*)ei)[i] : ((const int*)ei)[i];
}

__device__ __forceinline__ void fma4(float4& a, float w, const float4& v) {
    a.x += w * v.x; a.y += w * v.y; a.z += w * v.z; a.w += w * v.w;
}

__device__ __forceinline__ void cp16(uint32_t smem_dst, const void* gsrc) {
    asm volatile("cp.async.cg.shared.global [%0], [%1], 16;"
                 :: "r"(smem_dst), "l"(gsrc));
}
__device__ __forceinline__ void cp_commit() {
    asm volatile("cp.async.commit_group;");
}
template <int K>
__device__ __forceinline__ void cp_wait() {
    asm volatile("cp.async.wait_group %0;" :: "n"(K));
}

// ---------------------------------------------------------------------------
__global__ void __launch_bounds__(NT, MAX_CTA_PER_SM)
k_fused(const void* __restrict__ ei, const float4* __restrict__ x4,
        float4* __restrict__ out4, int E, int n, int batch, int nblocks) {
    __shared__ float4 sbuf[NWARP][PIPE][64];   // 1KB per stage per warp = 48KB

    const int tid      = blockIdx.x * NT + threadIdx.x;
    const int nthreads = nblocks * NT;

    // ---- Phase A: zero counters, detect index dtype -------------------------
    for (int i = tid; i < n; i += nthreads) g_deg[i] = 0;
    for (int i = tid; i < batch; i += nthreads) g_cntrow[i] = 0;
    if (tid == 0) g_spill = 0;

    if (blockIdx.x == 0) {
        __shared__ int bad;
        if (threadIdx.x == 0) bad = 0;
        __syncthreads();
        const long long* e64 = (const long long*)ei;
        int K = min(E, 2048);
        for (int t = threadIdx.x; t < K; t += NT) {
            long long v = e64[t];
            if (v < 0 || v >= (long long)n) bad = 1;
        }
        __syncthreads();
        if (threadIdx.x == 0) g_idx64 = bad ? 0 : 1;
    }

    grid_barrier(nblocks);

    // ---- Phase B: build deg + slot buckets (R7 scalar form) ------------------
    const int is64 = g_idx64;
    for (int i = tid; i < E; i += nthreads) {
        int src = load_idx(ei, i, is64);
        int dst = load_idx(ei, (long long)E + i, is64);
        atomicAdd(&g_deg[src], 1);
        if (dst < batch) {
            int slot = atomicAdd(&g_cntrow[dst], 1);
            if (slot < CAP) {
                g_slots[dst * CAP + slot] = src;
            } else {
                int p = atomicAdd(&g_spill, 1);
                if (p < MAX_SP) g_sp_edge[p] = make_int2(src, dst);
            }
        }
    }

    grid_barrier(nblocks);

    // ---- Phase C: gather, one warp per row, cp.async smem pipeline ----------
    const int lane   = threadIdx.x & 31;
    const int wib    = (threadIdx.x >> 5);         // warp in block
    const int gwarp  = tid >> 5;
    const int nwarps = nthreads >> 5;

    // per-lane smem byte addresses of this warp's ring (lane's two 16B cells)
    uint32_t sb_lo = (uint32_t)__cvta_generic_to_shared(&sbuf[wib][0][lane]);
    uint32_t sb_hi = (uint32_t)__cvta_generic_to_shared(&sbuf[wib][0][lane + 32]);

    for (int row = gwarp; row < batch; row += nwarps) {
        int mraw = g_cntrow[row];
        int m = (mraw > CAP) ? CAP : mraw;
        int dr = g_deg[row];
        float disr = (dr > 0) ? rsqrtf((float)dr) : 0.0f;

        float4 a0 = make_float4(0.f, 0.f, 0.f, 0.f);
        float4 a1 = make_float4(0.f, 0.f, 0.f, 0.f);

        const int* srow = g_slots + row * CAP;

        if (m <= 32) {
            // fast path: cp.async pipeline, lane-private smem cells
            int   psrc = 0;
            float pw   = 0.0f;
            if (lane < m) {
                psrc = srow[lane];
                pw = rsqrtf((float)g_deg[psrc]) * disr;   // deg[src] >= 1 always
            }

            int npre = min(m, PIPE);
            for (int k = 0; k < npre; k++) {
                int s = __shfl_sync(0xffffffff, psrc, k);
                const float* g = (const float*)(x4 + (size_t)s * D4);
                cp16(sb_lo + (uint32_t)k * 1024, g + lane * 4);
                cp16(sb_hi + (uint32_t)k * 1024, g + 128 + lane * 4);
                cp_commit();
            }

            for (int t = 0; t < m; t++) {
                if (t + PIPE <= m) cp_wait<PIPE - 1>();
                else               cp_wait<0>();

                int st = t % PIPE;
                float ww = __shfl_sync(0xffffffff, pw, t);
                float4 v0 = sbuf[wib][st][lane];
                float4 v1 = sbuf[wib][st][lane + 32];
                fma4(a0, ww, v0);
                fma4(a1, ww, v1);

                int nxt = t + PIPE;
                if (nxt < m) {
                    int s = __shfl_sync(0xffffffff, psrc, nxt);
                    const float* g = (const float*)(x4 + (size_t)s * D4);
                    cp16(sb_lo + (uint32_t)st * 1024, g + lane * 4);
                    cp16(sb_hi + (uint32_t)st * 1024, g + 128 + lane * 4);
                    cp_commit();
                }
            }
        } else {
            // slow path (rare): direct LDG, R7 form
            for (int base = 0; base < m; base += 32) {
                int e = base + lane;
                int cnt = min(32, m - base);
                int   psrc = 0;
                float pw   = 0.0f;
                if (e < m) {
                    psrc = srow[e];
                    pw = rsqrtf((float)g_deg[psrc]) * disr;
                }
                for (int t = 0; t < cnt; t++) {
                    int   s  = __shfl_sync(0xffffffff, psrc, t);
                    float ww = __shfl_sync(0xffffffff, pw, t);
                    const float4* xs = x4 + (size_t)s * D4;
                    float4 v0 = __ldg(&xs[lane]);
                    float4 v1 = __ldg(&xs[lane + 32]);
                    fma4(a0, ww, v0);
                    fma4(a1, ww, v1);
                }
            }
        }

        // Overflow fold (only the owning warp touches its spilled edges).
        if (mraw > CAP) {
            int sp = g_spill;
            if (sp > MAX_SP) sp = MAX_SP;
            for (int base = 0; base < sp; base += 32) {
                int e = base + lane;
                int cnt = min(32, sp - base);
                int   psrc = 0;
                float pw   = 0.0f;
                if (e < sp) {
                    int2 ed = g_sp_edge[e];
                    if (ed.y == row) {
                        psrc = ed.x;
                        pw = rsqrtf((float)g_deg[psrc]) * disr;
                    }
                }
                for (int t = 0; t < cnt; t++) {
                    float ww = __shfl_sync(0xffffffff, pw, t);
                    if (ww == 0.0f) continue;
                    int s = __shfl_sync(0xffffffff, psrc, t);
                    const float4* xs = x4 + (size_t)s * D4;
                    float4 v0 = __ldg(&xs[lane]);
                    float4 v1 = __ldg(&xs[lane + 32]);
                    fma4(a0, ww, v0);
                    fma4(a1, ww, v1);
                }
            }
        }

        const float4* xd = x4 + (size_t)row * D4;
        float4* o = out4 + (size_t)row * (OUTW / 4);
        o[lane]      = __ldg(&xd[lane]);
        o[lane + 32] = __ldg(&xd[lane + 32]);
        o[lane + 64] = a0;
        o[lane + 96] = a1;
    }
}

// ---------------------------------------------------------------------------
extern "C" void kernel_launch(void* const* d_in, const int* in_sizes, int n_in,
                              void* d_out, int out_size) {
    // Identify inputs by element count (robust to metadata ordering).
    int ix = 0, ie = -1;
    for (int i = 1; i < n_in; i++)
        if (in_sizes[i] > in_sizes[ix]) ix = i;
    for (int i = 0; i < n_in; i++) {
        if (i == ix || in_sizes[i] <= 1) continue;
        if (ie < 0 || in_sizes[i] > in_sizes[ie]) ie = i;
    }
    if (ie < 0) ie = (ix == 0) ? 1 : 0;

    const float* x  = (const float*)d_in[ix];
    const void*  ei = d_in[ie];

    int n     = in_sizes[ix] / D_FEAT;         // 20000
    int E     = in_sizes[ie] / 2;              // 320000
    int batch = out_size / OUTW;               // 4096

    // Co-resident grid: query achievable occupancy so the spin barrier is safe.
    static int nblocks = 0;
    if (nblocks == 0) {
        int smCount = 0;
        if (cudaDeviceGetAttribute(&smCount, cudaDevAttrMultiProcessorCount, 0)
            != cudaSuccess || smCount <= 0)
            smCount = 148;
        int perSM = 0;
        if (cudaOccupancyMaxActiveBlocksPerMultiprocessor(&perSM, k_fused, NT, 0)
            != cudaSuccess || perSM <= 0)
            perSM = 1;
        if (perSM > MAX_CTA_PER_SM) perSM = MAX_CTA_PER_SM;
        nblocks = smCount * perSM;
    }

    k_fused<<<nblocks, NT>>>(ei, (const float4*)x, (float4*)d_out,
                             E, n, batch, nblocks);
}

// round 13
// speedup vs baseline: 1.1780x; 1.0890x over previous
#include <cuda_runtime.h>
#include <stdint.h>

#define D_FEAT   256
#define D4       (D_FEAT / 4)     // 64 float4 per x row
#define OUTW     (2 * D_FEAT)     // 512 floats per output row
#define MAX_N    32768
#define MAX_B    8192
#define CAP      128              // slots per destination row (mean deg ~16, max ~45)
#define MAX_SP   65536            // spill capacity (normally 0 used)
#define NT       1024
#define MAX_CTA_PER_SM 1

// Scratch (no cudaMalloc allowed) — device globals
__device__ int   g_deg[MAX_N];
__device__ int   g_cntrow[MAX_B];
__device__ int   g_idx64;
__device__ int   g_spill;
__device__ int   g_slots[MAX_B * CAP];
__device__ int2  g_sp_edge[MAX_SP];

// generation-based grid barrier state (monotonic across graph replays)
__device__ int           g_bar_count;
__device__ volatile int  g_bar_gen;

__device__ __forceinline__ void grid_barrier(int nblocks) {
    __syncthreads();
    if (threadIdx.x == 0) {
        int gen = g_bar_gen;
        __threadfence();                       // make prior writes visible
        if (atomicAdd(&g_bar_count, 1) == nblocks - 1) {
            g_bar_count = 0;
            __threadfence();
            g_bar_gen = gen + 1;               // release
        } else {
            while (g_bar_gen == gen) __nanosleep(32);
            __threadfence();                   // acquire
        }
    }
    __syncthreads();
}

__device__ __forceinline__ int load_idx(const void* ei, long long i, int is64) {
    return is64 ? (int)((const long long*)ei)[i] : ((const int*)ei)[i];
}

__device__ __forceinline__ void fma4(float4& a, float w, const float4& v) {
    a.x += w * v.x; a.y += w * v.y; a.z += w * v.z; a.w += w * v.w;
}

__device__ __forceinline__ void bucket_edge(int src, int dst, int batch) {
    if (dst < batch) {
        int slot = atomicAdd(&g_cntrow[dst], 1);
        if (slot < CAP) {
            g_slots[dst * CAP + slot] = src;
        } else {
            int p = atomicAdd(&g_spill, 1);
            if (p < MAX_SP) g_sp_edge[p] = make_int2(src, dst);
        }
    }
}

// ---------------------------------------------------------------------------
__global__ void __launch_bounds__(NT, MAX_CTA_PER_SM)
k_fused(const void* __restrict__ ei, const float4* __restrict__ x4,
        float4* __restrict__ out4, int E, int n, int batch, int nblocks) {
    const int tid      = blockIdx.x * NT + threadIdx.x;
    const int nthreads = nblocks * NT;

    // ---- Phase A: zero counters, detect index dtype -------------------------
    for (int i = tid; i < n; i += nthreads) g_deg[i] = 0;
    for (int i = tid; i < batch; i += nthreads) g_cntrow[i] = 0;
    if (tid == 0) g_spill = 0;

    if (blockIdx.x == 0) {
        __shared__ int bad;
        if (threadIdx.x == 0) bad = 0;
        __syncthreads();
        const long long* e64 = (const long long*)ei;
        int K = min(E, 2048);
        for (int t = threadIdx.x; t < K; t += NT) {
            long long v = e64[t];
            if (v < 0 || v >= (long long)n) bad = 1;
        }
        __syncthreads();
        if (threadIdx.x == 0) g_idx64 = bad ? 0 : 1;
    }

    grid_barrier(nblocks);

    // ---- Phase B: build deg + slot buckets (2-edge batch, loads hoisted) ----
    const int is64 = g_idx64;
    {
        long long stride2 = (long long)nthreads * 2;
        for (long long i = (long long)tid * 2; i < E; i += stride2) {
            int has1 = (i + 1 < E);
            // hoist all index loads before any atomic
            int s0 = load_idx(ei, i, is64);
            int d0 = load_idx(ei, (long long)E + i, is64);
            int s1 = 0, d1 = batch;
            if (has1) {
                s1 = load_idx(ei, i + 1, is64);
                d1 = load_idx(ei, (long long)E + i + 1, is64);
            }
            // fire-and-forget degree REDs
            atomicAdd(&g_deg[s0], 1);
            if (has1) atomicAdd(&g_deg[s1], 1);
            // independent bucket chains (overlap the two ATOMG round trips)
            bucket_edge(s0, d0, batch);
            bucket_edge(s1, d1, batch);
        }
    }

    grid_barrier(nblocks);

    // ---- Phase C: gather, one warp per row (R7 form, verbatim) --------------
    const int lane   = threadIdx.x & 31;
    const int gwarp  = tid >> 5;
    const int nwarps = nthreads >> 5;

    for (int row = gwarp; row < batch; row += nwarps) {
        int mraw = g_cntrow[row];
        int m = (mraw > CAP) ? CAP : mraw;
        int dr = g_deg[row];
        float disr = (dr > 0) ? rsqrtf((float)dr) : 0.0f;

        float4 a0 = make_float4(0.f, 0.f, 0.f, 0.f);
        float4 a1 = make_float4(0.f, 0.f, 0.f, 0.f);

        const int* srow = g_slots + row * CAP;
        for (int base = 0; base < m; base += 32) {
            int e = base + lane;
            int cnt = min(32, m - base);
            int   psrc = 0;
            float pw   = 0.0f;
            if (e < m) {
                psrc = srow[e];
                pw = rsqrtf((float)g_deg[psrc]) * disr;   // deg[src] >= 1 always
            }
            for (int t = 0; t < cnt; t++) {
                int   s  = __shfl_sync(0xffffffff, psrc, t);
                float ww = __shfl_sync(0xffffffff, pw, t);
                const float4* xs = x4 + (size_t)s * D4;
                float4 v0 = __ldg(&xs[lane]);
                float4 v1 = __ldg(&xs[lane + 32]);
                fma4(a0, ww, v0);
                fma4(a1, ww, v1);
            }
        }

        // Overflow fold (only the owning warp touches its spilled edges).
        if (mraw > CAP) {
            int sp = g_spill;
            if (sp > MAX_SP) sp = MAX_SP;
            for (int base = 0; base < sp; base += 32) {
                int e = base + lane;
                int cnt = min(32, sp - base);
                int   psrc = 0;
                float pw   = 0.0f;
                if (e < sp) {
                    int2 ed = g_sp_edge[e];
                    if (ed.y == row) {
                        psrc = ed.x;
                        pw = rsqrtf((float)g_deg[psrc]) * disr;
                    }
                }
                for (int t = 0; t < cnt; t++) {
                    float ww = __shfl_sync(0xffffffff, pw, t);
                    if (ww == 0.0f) continue;
                    int s = __shfl_sync(0xffffffff, psrc, t);
                    const float4* xs = x4 + (size_t)s * D4;
                    float4 v0 = __ldg(&xs[lane]);
                    float4 v1 = __ldg(&xs[lane + 32]);
                    fma4(a0, ww, v0);
                    fma4(a1, ww, v1);
                }
            }
        }

        const float4* xd = x4 + (size_t)row * D4;
        float4* o = out4 + (size_t)row * (OUTW / 4);
        o[lane]      = __ldg(&xd[lane]);
        o[lane + 32] = __ldg(&xd[lane + 32]);
        o[lane + 64] = a0;
        o[lane + 96] = a1;
    }
}

// ---------------------------------------------------------------------------
extern "C" void kernel_launch(void* const* d_in, const int* in_sizes, int n_in,
                              void* d_out, int out_size) {
    // Identify inputs by element count (robust to metadata ordering).
    int ix = 0, ie = -1;
    for (int i = 1; i < n_in; i++)
        if (in_sizes[i] > in_sizes[ix]) ix = i;
    for (int i = 0; i < n_in; i++) {
        if (i == ix || in_sizes[i] <= 1) continue;
        if (ie < 0 || in_sizes[i] > in_sizes[ie]) ie = i;
    }
    if (ie < 0) ie = (ix == 0) ? 1 : 0;

    const float* x  = (const float*)d_in[ix];
    const void*  ei = d_in[ie];

    int n     = in_sizes[ix] / D_FEAT;         // 20000
    int E     = in_sizes[ie] / 2;              // 320000
    int batch = out_size / OUTW;               // 4096

    // Co-resident grid: query achievable occupancy so the spin barrier is safe.
    static int nblocks = 0;
    if (nblocks == 0) {
        int smCount = 0;
        if (cudaDeviceGetAttribute(&smCount, cudaDevAttrMultiProcessorCount, 0)
            != cudaSuccess || smCount <= 0)
            smCount = 148;
        int perSM = 0;
        if (cudaOccupancyMaxActiveBlocksPerMultiprocessor(&perSM, k_fused, NT, 0)
            != cudaSuccess || perSM <= 0)
            perSM = 1;
        if (perSM > MAX_CTA_PER_SM) perSM = MAX_CTA_PER_SM;
        nblocks = smCount * perSM;
    }

    k_fused<<<nblocks, NT>>>(ei, (const float4*)x, (float4*)d_out,
                             E, n, batch, nblocks);
}